// round 1
// baseline (speedup 1.0000x reference)
#include <cuda_runtime.h>
#include <cuda_bf16.h>
#include <cstdint>

// Problem constants
#define BB 64
#define TT 512
#define HH 768
#define KK 11
#define START_ID 9
#define NEGV (-10000.0f)

// Scratch for projected features [B][T][K]  (1.44 MB, static device global — allowed)
__device__ float g_feats[BB * TT * KK];

// ---------------------------------------------------------------------------
// Kernel 1: feats[b,t,k] = dot(embeds[b,t,:], W[k,:]) + bias[k]
// One warp per (b,t) row. W + bias staged in shared. float4 coalesced loads.
// ---------------------------------------------------------------------------
__global__ __launch_bounds__(256) void feats_kernel(
    const float* __restrict__ embeds,   // [B*T, H]
    const float* __restrict__ W,        // [K, H]
    const float* __restrict__ bias)     // [K]
{
    __shared__ float sW[KK][HH];   // 33792 B
    __shared__ float sb[KK];

    const int tid = threadIdx.x;
    for (int i = tid; i < KK * HH; i += blockDim.x) sW[i / HH][i % HH] = W[i];
    if (tid < KK) sb[tid] = bias[tid];
    __syncthreads();

    const int warp = tid >> 5;
    const int lane = tid & 31;
    const int row = blockIdx.x * (blockDim.x >> 5) + warp;   // b*T + t
    if (row >= BB * TT) return;

    const float4* e4 = reinterpret_cast<const float4*>(embeds + (size_t)row * HH);

    float acc[KK];
#pragma unroll
    for (int k = 0; k < KK; k++) acc[k] = 0.0f;

#pragma unroll
    for (int it = 0; it < HH / 128; it++) {          // 6 iterations
        float4 v = e4[it * 32 + lane];
        const int base = (it * 32 + lane) * 4;
#pragma unroll
        for (int k = 0; k < KK; k++) {
            acc[k] += v.x * sW[k][base + 0];
            acc[k] += v.y * sW[k][base + 1];
            acc[k] += v.z * sW[k][base + 2];
            acc[k] += v.w * sW[k][base + 3];
        }
    }

    // Butterfly reduce each of the 11 partials; lane k keeps result k.
    float outv = 0.0f;
#pragma unroll
    for (int k = 0; k < KK; k++) {
        float a = acc[k];
#pragma unroll
        for (int off = 16; off > 0; off >>= 1)
            a += __shfl_xor_sync(0xffffffffu, a, off);
        if (lane == k) outv = a + sb[k];
    }
    if (lane < KK) g_feats[(size_t)row * KK + lane] = outv;
}

// ---------------------------------------------------------------------------
// Kernel 2: Viterbi scan + backtrack, one block per batch element.
//   delta0 = NEG everywhere except START_ID = 0
//   for t in 1..T-1:
//     score[i][j] = trans[i][j] + delta[j]
//     psi[t-1][i] = argmax_j (first max)
//     delta'[i]   = max_j + feat[t][i]
//   score = max_i delta ; last_tag = argmax_i (first max)
//   backtrack via psi.
// Output layout: out[0..B) = score ; out[B + b*T + t] = (float)path[b][t]
// ---------------------------------------------------------------------------
__global__ __launch_bounds__(128) void viterbi_kernel(
    const float* __restrict__ trans,    // [K, K]
    float* __restrict__ out)            // [B + B*T]
{
    const int b = blockIdx.x;
    const int tid = threadIdx.x;

    __shared__ float sfeat[TT * KK];                 // 22528 B
    __shared__ unsigned char spsi[(TT - 1) * KK];    // 5621 B
    __shared__ float sdelta[2][16];
    __shared__ int   spath[TT];
    __shared__ float sscore;

    // Stage this batch's feats (5632 floats, 16B-aligned).
    const float4* f4 = reinterpret_cast<const float4*>(g_feats + (size_t)b * TT * KK);
    float4* s4 = reinterpret_cast<float4*>(sfeat);
    for (int i = tid; i < (TT * KK) / 4; i += blockDim.x) s4[i] = f4[i];

    if (tid < 16) {
        sdelta[0][tid] = (tid == START_ID) ? 0.0f : NEGV;
        sdelta[1][tid] = -3.0e38f;
    }
    __syncthreads();

    if (tid < 32) {
        float tr[KK];
        if (tid < KK) {
#pragma unroll
            for (int j = 0; j < KK; j++) tr[j] = trans[tid * KK + j];
        }

        for (int t = 1; t < TT; t++) {
            const int cur = (t - 1) & 1;
            const int nxt = t & 1;
            if (tid < KK) {
                float best = -3.4e38f;
                int bi = 0;
#pragma unroll
                for (int j = 0; j < KK; j++) {
                    float s = tr[j] + sdelta[cur][j];
                    if (s > best) { best = s; bi = j; }   // strict > : first max wins
                }
                sdelta[nxt][tid] = best + sfeat[t * KK + tid];
                spsi[(t - 1) * KK + tid] = (unsigned char)bi;
            }
            __syncwarp();
        }

        if (tid == 0) {
            const int fin = (TT - 1) & 1;   // buffer holding final delta
            float best = -3.4e38f;
            int bi = 0;
#pragma unroll
            for (int i = 0; i < KK; i++) {
                float v = sdelta[fin][i];
                if (v > best) { best = v; bi = i; }
            }
            sscore = best;
            spath[TT - 1] = bi;
            int tag = bi;
            for (int t = TT - 2; t >= 0; t--) {
                tag = spsi[t * KK + tag];
                spath[t] = tag;
            }
        }
    }
    __syncthreads();

    if (tid == 0) out[b] = sscore;
    for (int t = tid; t < TT; t += blockDim.x)
        out[BB + (size_t)b * TT + t] = (float)spath[t];
}

// ---------------------------------------------------------------------------
extern "C" void kernel_launch(void* const* d_in, const int* in_sizes, int n_in,
                              void* d_out, int out_size)
{
    const float* embeds = (const float*)d_in[0];   // [B,T,H]
    const float* W_fc   = (const float*)d_in[1];   // [K,H]
    const float* b_fc   = (const float*)d_in[2];   // [K]
    const float* trans  = (const float*)d_in[3];   // [K,K]
    float* out = (float*)d_out;

    const int warpsPerBlock = 8;
    const int rows = BB * TT;
    feats_kernel<<<rows / warpsPerBlock, warpsPerBlock * 32>>>(embeds, W_fc, b_fc);
    viterbi_kernel<<<BB, 128>>>(trans, out);
}

// round 2
// speedup vs baseline: 1.0135x; 1.0135x over previous
#include <cuda_runtime.h>
#include <cstdint>

#define BB 64
#define TT 512
#define HH 768
#define KK 11
#define START_ID 9
#define NEGV (-10000.0f)

#define NROWS (BB*TT)            // 32768
#define KSPLIT 4
#define KRANGE (HH/KSPLIT)       // 192
#define ROWS_PB 512              // rows per block
#define CHUNK_K 8
#define SA_STRIDE 10

__device__ __align__(16) float g_part[KSPLIT][NROWS*KK];
__device__ __align__(16) float g_feats[NROWS*KK];

// ---------------------------------------------------------------------------
// Kernel 1: partial feats. Grid = 64 row-blocks x 4 k-splits = 256 blocks.
// Each thread owns 2 rows, accumulates 11 outputs per row as f32x2 pairs
// (even/odd k in lo/hi halves) via fma.rn.f32x2. Weights are broadcast LDS.64.
// ---------------------------------------------------------------------------
__global__ __launch_bounds__(256) void feats_kernel(
    const float* __restrict__ A,      // [NROWS, HH]
    const float* __restrict__ W,      // [KK, HH]
    const float* __restrict__ bias)   // [KK]
{
    __shared__ float sA[ROWS_PB * SA_STRIDE];        // 20480 B
    __shared__ float sW2[(KRANGE/2) * 2 * KK];       // 8448 B: [kpair][c][2]

    const int tid = threadIdx.x;
    const int rowBlk = blockIdx.x & 63;
    const int ks = blockIdx.x >> 6;                  // 0..3
    const int rowBase = rowBlk * ROWS_PB;
    const int k0 = ks * KRANGE;

    // stage weight pairs: sW2[kp*22 + c*2 + h] = W[c][k0 + 2*kp + h]
    for (int i = tid; i < (KRANGE/2) * 2 * KK; i += 256) {
        int kp = i / (2*KK);
        int r = i - kp * (2*KK);
        int c = r >> 1;
        int h = r & 1;
        sW2[i] = W[c * HH + k0 + 2*kp + h];
    }

    unsigned long long acc0[KK], acc1[KK];
#pragma unroll
    for (int c = 0; c < KK; c++) { acc0[c] = 0ull; acc1[c] = 0ull; }

    const int r0 = tid, r1 = tid + 256;
    const unsigned long long* sW64 = reinterpret_cast<const unsigned long long*>(sW2);

    // prologue loads for chunk 0
    float4 v0a, v0b, v1a, v1b;
    {
        const int kc = k0;
        v0a = *(const float4*)&A[(size_t)(rowBase + r0) * HH + kc];
        v0b = *(const float4*)&A[(size_t)(rowBase + r0) * HH + kc + 4];
        v1a = *(const float4*)&A[(size_t)(rowBase + r1) * HH + kc];
        v1b = *(const float4*)&A[(size_t)(rowBase + r1) * HH + kc + 4];
    }

    for (int ch = 0; ch < KRANGE / CHUNK_K; ++ch) {   // 24 chunks
        // store staged regs to smem (stride-10 rows, 8B-aligned float2 stores)
        *(float2*)&sA[r0 * SA_STRIDE + 0] = make_float2(v0a.x, v0a.y);
        *(float2*)&sA[r0 * SA_STRIDE + 2] = make_float2(v0a.z, v0a.w);
        *(float2*)&sA[r0 * SA_STRIDE + 4] = make_float2(v0b.x, v0b.y);
        *(float2*)&sA[r0 * SA_STRIDE + 6] = make_float2(v0b.z, v0b.w);
        *(float2*)&sA[r1 * SA_STRIDE + 0] = make_float2(v1a.x, v1a.y);
        *(float2*)&sA[r1 * SA_STRIDE + 2] = make_float2(v1a.z, v1a.w);
        *(float2*)&sA[r1 * SA_STRIDE + 4] = make_float2(v1b.x, v1b.y);
        *(float2*)&sA[r1 * SA_STRIDE + 6] = make_float2(v1b.z, v1b.w);
        __syncthreads();

        // issue next chunk's global loads (consumed next iteration)
        if (ch + 1 < KRANGE / CHUNK_K) {
            const int kc = k0 + (ch + 1) * CHUNK_K;
            v0a = *(const float4*)&A[(size_t)(rowBase + r0) * HH + kc];
            v0b = *(const float4*)&A[(size_t)(rowBase + r0) * HH + kc + 4];
            v1a = *(const float4*)&A[(size_t)(rowBase + r1) * HH + kc];
            v1b = *(const float4*)&A[(size_t)(rowBase + r1) * HH + kc + 4];
        }

#pragma unroll
        for (int kp = 0; kp < CHUNK_K / 2; ++kp) {    // 4 k-pairs
            unsigned long long a0 = *(const unsigned long long*)&sA[r0 * SA_STRIDE + kp * 2];
            unsigned long long a1 = *(const unsigned long long*)&sA[r1 * SA_STRIDE + kp * 2];
            const int wbase = (ch * 4 + kp) * KK;     // in 64-bit units
#pragma unroll
            for (int c = 0; c < KK; c++) {
                unsigned long long w = sW64[wbase + c];
                asm("fma.rn.f32x2 %0, %1, %2, %0;" : "+l"(acc0[c]) : "l"(a0), "l"(w));
                asm("fma.rn.f32x2 %0, %1, %2, %0;" : "+l"(acc1[c]) : "l"(a1), "l"(w));
            }
        }
        __syncthreads();
    }

    // epilogue: fold halves, add bias on split 0, write partials
#pragma unroll
    for (int c = 0; c < KK; c++) {
        float2 p0 = *reinterpret_cast<float2*>(&acc0[c]);
        float2 p1 = *reinterpret_cast<float2*>(&acc1[c]);
        float bc = (ks == 0) ? __ldg(&bias[c]) : 0.0f;
        g_part[ks][(size_t)(rowBase + r0) * KK + c] = p0.x + p0.y + bc;
        g_part[ks][(size_t)(rowBase + r1) * KK + c] = p1.x + p1.y + bc;
    }
}

// ---------------------------------------------------------------------------
// Kernel 2: sum the 4 k-split partials -> g_feats. 360448 floats = 90112 float4.
// ---------------------------------------------------------------------------
__global__ __launch_bounds__(256) void reduce_kernel()
{
    int i = blockIdx.x * 256 + threadIdx.x;          // < 90112
    const float4* p0 = (const float4*)g_part[0];
    const float4* p1 = (const float4*)g_part[1];
    const float4* p2 = (const float4*)g_part[2];
    const float4* p3 = (const float4*)g_part[3];
    float4 a = p0[i], b = p1[i], c = p2[i], d = p3[i];
    float4 s;
    s.x = a.x + b.x + c.x + d.x;
    s.y = a.y + b.y + c.y + d.y;
    s.z = a.z + b.z + c.z + d.z;
    s.w = a.w + b.w + c.w + d.w;
    ((float4*)g_feats)[i] = s;
}

// ---------------------------------------------------------------------------
// Kernel 3: Viterbi. One block per batch. Warp 0 runs the 511-step scan with
// delta replicated into every lane's registers via shfl all-gather. psi goes
// to smem. Then a chunked (exact, integer) parallel backtrack.
// ---------------------------------------------------------------------------
__global__ __launch_bounds__(192) void viterbi_kernel(
    const float* __restrict__ trans,   // [KK, KK]
    float* __restrict__ out)           // [BB + BB*TT]
{
    const int b = blockIdx.x;
    const int tid = threadIdx.x;

    __shared__ unsigned char spsi[(TT - 1) * KK];          // 5621 B
    __shared__ unsigned char s_pathseg[16][KK][32];        // 5632 B
    __shared__ unsigned char s_esel[16];
    __shared__ int s_lasttag;
    __shared__ float s_score;

    if (tid < 32) {
        const int lane = tid;
        const int ic = lane < KK ? lane : KK - 1;

        float tr[KK];
#pragma unroll
        for (int j = 0; j < KK; j++) tr[j] = __ldg(&trans[ic * KK + j]);

        float d[KK];
#pragma unroll
        for (int j = 0; j < KK; j++) d[j] = (j == START_ID) ? 0.0f : NEGV;

        const float* fptr = g_feats + (size_t)b * TT * KK + ic;

        float fbuf[8];
#pragma unroll
        for (int s = 0; s < 8; s++) fbuf[s] = __ldg(&fptr[(1 + s) * KK]);

#define VSTEP(T_, FV_)                                                        \
        {                                                                     \
            float s0 = tr[0] + d[0], s1 = tr[1] + d[1], s2 = tr[2] + d[2];    \
            float s3 = tr[3] + d[3], s4 = tr[4] + d[4], s5 = tr[5] + d[5];    \
            float s6 = tr[6] + d[6], s7 = tr[7] + d[7], s8 = tr[8] + d[8];    \
            float s9 = tr[9] + d[9], s10 = tr[10] + d[10];                    \
            float m01 = fmaxf(s0, s1), m23 = fmaxf(s2, s3);                   \
            float m45 = fmaxf(s4, s5), m67 = fmaxf(s6, s7);                   \
            float m89 = fmaxf(s8, s9);                                        \
            float m0123 = fmaxf(m01, m23), m4567 = fmaxf(m45, m67);           \
            float m8910 = fmaxf(m89, s10);                                    \
            float m = fmaxf(fmaxf(m0123, m4567), m8910);                      \
            float new_d = m + (FV_);                                          \
            unsigned msk = (s0 == m ? 1u : 0u) | (s1 == m ? 2u : 0u) |        \
                           (s2 == m ? 4u : 0u) | (s3 == m ? 8u : 0u) |        \
                           (s4 == m ? 16u : 0u) | (s5 == m ? 32u : 0u) |      \
                           (s6 == m ? 64u : 0u) | (s7 == m ? 128u : 0u) |     \
                           (s8 == m ? 256u : 0u) | (s9 == m ? 512u : 0u) |    \
                           (s10 == m ? 1024u : 0u);                           \
            int psi = __ffs(msk) - 1;                                         \
            if (lane < KK) spsi[((T_) - 1) * KK + lane] = (unsigned char)psi; \
            d[0] = __shfl_sync(0xffffffffu, new_d, 0);                        \
            d[1] = __shfl_sync(0xffffffffu, new_d, 1);                        \
            d[2] = __shfl_sync(0xffffffffu, new_d, 2);                        \
            d[3] = __shfl_sync(0xffffffffu, new_d, 3);                        \
            d[4] = __shfl_sync(0xffffffffu, new_d, 4);                        \
            d[5] = __shfl_sync(0xffffffffu, new_d, 5);                        \
            d[6] = __shfl_sync(0xffffffffu, new_d, 6);                        \
            d[7] = __shfl_sync(0xffffffffu, new_d, 7);                        \
            d[8] = __shfl_sync(0xffffffffu, new_d, 8);                        \
            d[9] = __shfl_sync(0xffffffffu, new_d, 9);                        \
            d[10] = __shfl_sync(0xffffffffu, new_d, 10);                      \
        }

        int t = 1;
        for (int blk = 0; blk < 63; ++blk) {          // t = 1..504
#pragma unroll
            for (int u = 0; u < 8; ++u) {
                float f = fbuf[u];
                if (t + 8 <= TT - 1) fbuf[u] = __ldg(&fptr[(t + 8) * KK]);
                VSTEP(t, f);
                ++t;
            }
        }
#pragma unroll
        for (int u = 0; u < 7; ++u) {                 // t = 505..511
            float f = fbuf[u];
            VSTEP(t, f);
            ++t;
        }
#undef VSTEP

        // final score / last tag (identical in all lanes)
        {
            float m01 = fmaxf(d[0], d[1]), m23 = fmaxf(d[2], d[3]);
            float m45 = fmaxf(d[4], d[5]), m67 = fmaxf(d[6], d[7]);
            float m89 = fmaxf(d[8], d[9]);
            float m = fmaxf(fmaxf(fmaxf(m01, m23), fmaxf(m45, m67)),
                            fmaxf(m89, d[10]));
            unsigned msk = 0;
#pragma unroll
            for (int j = 0; j < KK; j++) msk |= (d[j] == m) ? (1u << j) : 0u;
            if (lane == 0) {
                s_score = m;
                s_lasttag = __ffs(msk) - 1;
            }
        }
    }
    __syncthreads();

    // ---- chunked backtrack: 16 chunks of 32 positions ----
    if (tid < 165) {                       // chunks 0..14, all 11 candidate tags
        const int c = tid / KK;
        const int e = tid - c * KK;
        const int tb = 32 * c;
        int tag = e;                       // candidate tag at position tb+32
        for (int t = tb + 32; t > tb; --t) {
            tag = spsi[(t - 1) * KK + tag];
            s_pathseg[c][e][t - 1 - tb] = (unsigned char)tag;
        }
    } else if (tid == 165) {               // chunk 15 from the known last tag
        int tag = s_lasttag;
        s_pathseg[15][0][31] = (unsigned char)tag;
        for (int t = TT - 1; t > 480; --t) {
            tag = spsi[(t - 1) * KK + tag];
            s_pathseg[15][0][t - 1 - 480] = (unsigned char)tag;
        }
    }
    __syncthreads();

    if (tid == 0) {
        s_esel[15] = 0;
        int btag = s_pathseg[15][0][0];    // tag at position 480
        for (int c = 14; c >= 0; --c) {
            s_esel[c] = (unsigned char)btag;
            btag = s_pathseg[c][btag][0];  // tag at position 32c
        }
    }
    __syncthreads();

    if (tid == 0) out[b] = s_score;
    for (int p = tid; p < TT; p += 192) {
        int c = p >> 5;
        out[BB + (size_t)b * TT + p] = (float)s_pathseg[c][s_esel[c]][p & 31];
    }
}

// ---------------------------------------------------------------------------
extern "C" void kernel_launch(void* const* d_in, const int* in_sizes, int n_in,
                              void* d_out, int out_size)
{
    const float* embeds = (const float*)d_in[0];   // [B,T,H]
    const float* W_fc   = (const float*)d_in[1];   // [K,H]
    const float* b_fc   = (const float*)d_in[2];   // [K]
    const float* trans  = (const float*)d_in[3];   // [K,K]
    float* out = (float*)d_out;

    feats_kernel<<<256, 256>>>(embeds, W_fc, b_fc);
    reduce_kernel<<<(NROWS * KK / 4) / 256, 256>>>();
    viterbi_kernel<<<BB, 192>>>(trans, out);
}

// round 3
// speedup vs baseline: 1.4345x; 1.4153x over previous
#include <cuda_runtime.h>
#include <cstdint>

#define BB 64
#define TT 512
#define HH 768
#define KK 11
#define START_ID 9
#define NEGV (-10000.0f)
#define NROWS (BB*TT)            // 32768

__device__ __align__(16) float g_feats[NROWS * KK];

// ---------------------------------------------------------------------------
// Kernel 1: feats[row][k] = dot(A[row,:], W[k,:]) + bias[k]
// 1024 blocks x 256 threads. Each warp owns 4 rows. A goes straight to
// registers (coalesced, lane-stride-1 in h). W transposed in smem with
// stride 11 (odd -> conflict-free scalar LDS). Butterfly reduction.
// ---------------------------------------------------------------------------
__global__ __launch_bounds__(256) void feats_kernel(
    const float* __restrict__ A,      // [NROWS, HH]
    const float* __restrict__ W,      // [KK, HH]
    const float* __restrict__ bias)   // [KK]
{
    __shared__ float sWt[HH * KK];    // [h*11 + k], 33792 B

    const int tid = threadIdx.x;
    // coalesced read of W, scattered STS into transposed layout
    for (int i = tid; i < HH * KK; i += 256) {
        int k = i / HH, h = i - k * HH;
        sWt[h * KK + k] = W[i];
    }
    __syncthreads();

    const int lane = tid & 31;
    const int warp = tid >> 5;
    const int rowBase = blockIdx.x * 32 + warp * 4;

    float acc[4][KK];
#pragma unroll
    for (int r = 0; r < 4; r++)
#pragma unroll
        for (int k = 0; k < KK; k++) acc[r][k] = 0.0f;

#pragma unroll
    for (int w = 0; w < 6; w++) {                 // windows of 128 h
        float a[4][4];
#pragma unroll
        for (int r = 0; r < 4; r++)
#pragma unroll
            for (int s = 0; s < 4; s++)
                a[r][s] = A[(size_t)(rowBase + r) * HH + w * 128 + s * 32 + lane];
#pragma unroll
        for (int s = 0; s < 4; s++) {
            float wr[KK];
            const int hb = (w * 128 + s * 32 + lane) * KK;
#pragma unroll
            for (int k = 0; k < KK; k++) wr[k] = sWt[hb + k];
#pragma unroll
            for (int r = 0; r < 4; r++)
#pragma unroll
                for (int k = 0; k < KK; k++)
                    acc[r][k] = fmaf(a[r][s], wr[k], acc[r][k]);
        }
    }

    // butterfly sum over the 32 lanes for each of 44 partials
#pragma unroll
    for (int r = 0; r < 4; r++)
#pragma unroll
        for (int k = 0; k < KK; k++) {
            float v = acc[r][k];
            v += __shfl_xor_sync(0xffffffffu, v, 16);
            v += __shfl_xor_sync(0xffffffffu, v, 8);
            v += __shfl_xor_sync(0xffffffffu, v, 4);
            v += __shfl_xor_sync(0xffffffffu, v, 2);
            v += __shfl_xor_sync(0xffffffffu, v, 1);
            acc[r][k] = v;
        }

    if (lane == 0) {
#pragma unroll
        for (int r = 0; r < 4; r++)
#pragma unroll
            for (int k = 0; k < KK; k++)
                g_feats[(size_t)(rowBase + r) * KK + k] = acc[r][k] + __ldg(&bias[k]);
    }
}

// ---------------------------------------------------------------------------
// psi recompute: argmax_j (trans[tag][j] + delta[t-1][j]), first-max wins.
// Bit-exact vs the scan: same FADDs, max is order-invariant, equality mask.
// ---------------------------------------------------------------------------
__device__ __forceinline__ int psi_step(const float* __restrict__ strans,
                                        const float* __restrict__ sdelta,
                                        int t, int tag)
{
    const float* tr = strans + tag * KK;
    const float* d = sdelta + (t - 1) * 12;
    float s[KK];
#pragma unroll
    for (int j = 0; j < KK; j++) s[j] = tr[j] + d[j];
    float m = s[0];
#pragma unroll
    for (int j = 1; j < KK; j++) m = fmaxf(m, s[j]);
    unsigned msk = 0;
#pragma unroll
    for (int j = 0; j < KK; j++) msk |= (s[j] == m) ? (1u << j) : 0u;
    return __ffs(msk) - 1;
}

// ---------------------------------------------------------------------------
// Kernel 2: Viterbi. One block per batch.
// Warp 0: psi-free serial scan; delta[t] stored to smem each step (doubles as
// the broadcast mechanism: STS -> syncwarp -> 3x LDS.128).
// Then: chunked parallel backtrack that recomputes psi from stored deltas.
// ---------------------------------------------------------------------------
__global__ __launch_bounds__(192) void viterbi_kernel(
    const float* __restrict__ trans,   // [KK, KK]
    float* __restrict__ out)           // [BB + BB*TT]
{
    const int b = blockIdx.x;
    const int tid = threadIdx.x;

    __shared__ float sdelta[TT * 12];                 // 24576 B, [t*12+j]
    __shared__ float strans[KK * KK];                 // 484 B
    __shared__ unsigned char s_pathseg[16][KK][32];   // 5632 B
    __shared__ unsigned char s_esel[16];
    __shared__ int s_lasttag;
    __shared__ float s_score;

    for (int i = tid; i < KK * KK; i += 192) strans[i] = trans[i];
    if (tid < 12) sdelta[tid] = (tid == START_ID) ? 0.0f : NEGV;   // t=0 row
    __syncthreads();

    if (tid < 32) {
        const int lane = tid;
        const int ic = lane < KK ? lane : KK - 1;

        float tr[KK];
#pragma unroll
        for (int j = 0; j < KK; j++) tr[j] = strans[ic * KK + j];

        const float* fptr = g_feats + (size_t)b * TT * KK + ic;
        float fbuf[8];
#pragma unroll
        for (int s = 0; s < 8; s++) fbuf[s] = __ldg(&fptr[(1 + s) * KK]);

        float4 dA = *(const float4*)&sdelta[0];
        float4 dB = *(const float4*)&sdelta[4];
        float4 dC = *(const float4*)&sdelta[8];

#define VSTEP(T_, FV_)                                                         \
        {                                                                      \
            float s0 = tr[0] + dA.x, s1 = tr[1] + dA.y;                        \
            float s2 = tr[2] + dA.z, s3 = tr[3] + dA.w;                        \
            float s4 = tr[4] + dB.x, s5 = tr[5] + dB.y;                        \
            float s6 = tr[6] + dB.z, s7 = tr[7] + dB.w;                        \
            float s8 = tr[8] + dC.x, s9 = tr[9] + dC.y, s10 = tr[10] + dC.z;   \
            float m01 = fmaxf(s0, s1), m23 = fmaxf(s2, s3);                    \
            float m45 = fmaxf(s4, s5), m67 = fmaxf(s6, s7);                    \
            float m89 = fmaxf(s8, s9);                                         \
            float m = fmaxf(fmaxf(fmaxf(m01, m23), fmaxf(m45, m67)),           \
                            fmaxf(m89, s10));                                  \
            float nd = m + (FV_);                                              \
            if (lane < KK) sdelta[(T_) * 12 + lane] = nd;                      \
            __syncwarp();                                                      \
            dA = *(const float4*)&sdelta[(T_) * 12];                           \
            dB = *(const float4*)&sdelta[(T_) * 12 + 4];                       \
            dC = *(const float4*)&sdelta[(T_) * 12 + 8];                       \
        }

        int t = 1;
        for (int blk = 0; blk < 63; ++blk) {          // t = 1..504
#pragma unroll
            for (int u = 0; u < 8; ++u) {
                float f = fbuf[u];
                if (t + 8 <= TT - 1) fbuf[u] = __ldg(&fptr[(t + 8) * KK]);
                VSTEP(t, f);
                ++t;
            }
        }
#pragma unroll
        for (int u = 0; u < 7; ++u) {                 // t = 505..511
            float f = fbuf[u];
            VSTEP(t, f);
            ++t;
        }
#undef VSTEP

        // final score / last tag (all lanes identical)
        {
            float m = fmaxf(fmaxf(fmaxf(fmaxf(dA.x, dA.y), fmaxf(dA.z, dA.w)),
                                  fmaxf(fmaxf(dB.x, dB.y), fmaxf(dB.z, dB.w))),
                            fmaxf(fmaxf(dC.x, dC.y), dC.z));
            unsigned msk = (dA.x == m ? 1u : 0u) | (dA.y == m ? 2u : 0u) |
                           (dA.z == m ? 4u : 0u) | (dA.w == m ? 8u : 0u) |
                           (dB.x == m ? 16u : 0u) | (dB.y == m ? 32u : 0u) |
                           (dB.z == m ? 64u : 0u) | (dB.w == m ? 128u : 0u) |
                           (dC.x == m ? 256u : 0u) | (dC.y == m ? 512u : 0u) |
                           (dC.z == m ? 1024u : 0u);
            if (lane == 0) {
                s_score = m;
                s_lasttag = __ffs(msk) - 1;
            }
        }
    }
    __syncthreads();

    // ---- chunked backtrack, psi recomputed from stored deltas ----
    if (tid < 165) {                       // chunks 0..14 x 11 entry tags
        const int c = tid / KK;
        const int e = tid - c * KK;
        const int tb = 32 * c;
        int tag = e;                       // candidate tag at position tb+32
        for (int t = tb + 32; t > tb; --t) {
            tag = psi_step(strans, sdelta, t, tag);
            s_pathseg[c][e][t - 1 - tb] = (unsigned char)tag;
        }
    } else if (tid == 165) {               // chunk 15 from known last tag
        int tag = s_lasttag;
        s_pathseg[15][0][31] = (unsigned char)tag;
        for (int t = TT - 1; t > 480; --t) {
            tag = psi_step(strans, sdelta, t, tag);
            s_pathseg[15][0][t - 1 - 480] = (unsigned char)tag;
        }
    }
    __syncthreads();

    if (tid == 0) {
        s_esel[15] = 0;
        int btag = s_pathseg[15][0][0];    // tag at position 480
        for (int c = 14; c >= 0; --c) {
            s_esel[c] = (unsigned char)btag;
            btag = s_pathseg[c][btag][0];  // tag at position 32c
        }
    }
    __syncthreads();

    if (tid == 0) out[b] = s_score;
    for (int p = tid; p < TT; p += 192) {
        int c = p >> 5;
        out[BB + (size_t)b * TT + p] = (float)s_pathseg[c][s_esel[c]][p & 31];
    }
}

// ---------------------------------------------------------------------------
extern "C" void kernel_launch(void* const* d_in, const int* in_sizes, int n_in,
                              void* d_out, int out_size)
{
    const float* embeds = (const float*)d_in[0];   // [B,T,H]
    const float* W_fc   = (const float*)d_in[1];   // [K,H]
    const float* b_fc   = (const float*)d_in[2];   // [K]
    const float* trans  = (const float*)d_in[3];   // [K,K]
    float* out = (float*)d_out;

    feats_kernel<<<1024, 256>>>(embeds, W_fc, b_fc);
    viterbi_kernel<<<BB, 192>>>(trans, out);
}

// round 5
// speedup vs baseline: 1.6668x; 1.1620x over previous
#include <cuda_runtime.h>
#include <cstdint>

#define BB 64
#define TT 512
#define HH 768
#define KK 11
#define START_ID 9
#define NEGV (-10000.0f)
#define NROWS (BB*TT)            // 32768

__device__ __align__(16) float g_feats[NROWS * KK];

// ---------------------------------------------------------------------------
// Kernel 1: feats[row][k] = dot(A[row,:], W[k,:]) + bias[k]   (at DRAM roofline)
// ---------------------------------------------------------------------------
__global__ __launch_bounds__(256) void feats_kernel(
    const float* __restrict__ A,      // [NROWS, HH]
    const float* __restrict__ W,      // [KK, HH]
    const float* __restrict__ bias)   // [KK]
{
    __shared__ float sWt[HH * KK];    // [h*11 + k], 33792 B

    const int tid = threadIdx.x;
    for (int i = tid; i < HH * KK; i += 256) {
        int k = i / HH, h = i - k * HH;
        sWt[h * KK + k] = W[i];
    }
    __syncthreads();

    const int lane = tid & 31;
    const int warp = tid >> 5;
    const int rowBase = blockIdx.x * 32 + warp * 4;

    float acc[4][KK];
#pragma unroll
    for (int r = 0; r < 4; r++)
#pragma unroll
        for (int k = 0; k < KK; k++) acc[r][k] = 0.0f;

#pragma unroll
    for (int w = 0; w < 6; w++) {
        float a[4][4];
#pragma unroll
        for (int r = 0; r < 4; r++)
#pragma unroll
            for (int s = 0; s < 4; s++)
                a[r][s] = A[(size_t)(rowBase + r) * HH + w * 128 + s * 32 + lane];
#pragma unroll
        for (int s = 0; s < 4; s++) {
            float wr[KK];
            const int hb = (w * 128 + s * 32 + lane) * KK;
#pragma unroll
            for (int k = 0; k < KK; k++) wr[k] = sWt[hb + k];
#pragma unroll
            for (int r = 0; r < 4; r++)
#pragma unroll
                for (int k = 0; k < KK; k++)
                    acc[r][k] = fmaf(a[r][s], wr[k], acc[r][k]);
        }
    }

#pragma unroll
    for (int r = 0; r < 4; r++)
#pragma unroll
        for (int k = 0; k < KK; k++) {
            float v = acc[r][k];
            v += __shfl_xor_sync(0xffffffffu, v, 16);
            v += __shfl_xor_sync(0xffffffffu, v, 8);
            v += __shfl_xor_sync(0xffffffffu, v, 4);
            v += __shfl_xor_sync(0xffffffffu, v, 2);
            v += __shfl_xor_sync(0xffffffffu, v, 1);
            acc[r][k] = v;
        }

    if (lane == 0) {
#pragma unroll
        for (int r = 0; r < 4; r++)
#pragma unroll
            for (int k = 0; k < KK; k++)
                g_feats[(size_t)(rowBase + r) * KK + k] = acc[r][k] + __ldg(&bias[k]);
    }
}

// ---------------------------------------------------------------------------
// psi recompute: argmax_j (trans[tag][j] + delta[t-1][j]), first-max wins.
// Bit-exact vs the scan (same FADDs; max is order-invariant).
// ---------------------------------------------------------------------------
__device__ __forceinline__ int psi_step(const float* __restrict__ strans,
                                        const float* __restrict__ sdelta,
                                        int t, int tag)
{
    const float* tr = strans + tag * KK;
    const float* d = sdelta + (t - 1) * 12;
    float s[KK];
#pragma unroll
    for (int j = 0; j < KK; j++) s[j] = tr[j] + d[j];
    float m = s[0];
#pragma unroll
    for (int j = 1; j < KK; j++) m = fmaxf(m, s[j]);
    unsigned msk = 0;
#pragma unroll
    for (int j = 0; j < KK; j++) msk |= (s[j] == m) ? (1u << j) : 0u;
    return __ffs(msk) - 1;
}

// ---------------------------------------------------------------------------
// Kernel 2: Viterbi. One block per batch.
// Scan: delta lives in registers of every lane of warp 0; per-step broadcast
// via 11 SHFL.IDX; delta history written to smem fire-and-forget (read only
// after the loop). Feats read from smem via a 7-deep LDS ring. 511 = 7*73.
// Then chunked parallel backtrack recomputing psi from the stored deltas.
// ---------------------------------------------------------------------------
__global__ __launch_bounds__(192) void viterbi_kernel(
    const float* __restrict__ trans,   // [KK, KK]
    float* __restrict__ out)           // [BB + BB*TT]
{
    const int b = blockIdx.x;
    const int tid = threadIdx.x;

    __shared__ float sfeat[TT * KK];                  // 22528 B, [t*11+k]
    __shared__ float sdelta[TT * 12];                 // 24576 B, [t*12+j]
    __shared__ float strans[KK * KK];                 // 484 B
    __shared__ unsigned char s_pathseg[16][KK][32];   // 5632 B
    __shared__ unsigned char s_esel[16];
    __shared__ int s_lasttag;
    __shared__ float s_score;

    // stage this batch's feats + transitions
    {
        const float4* f4 = reinterpret_cast<const float4*>(g_feats + (size_t)b * TT * KK);
        float4* s4 = reinterpret_cast<float4*>(sfeat);
        for (int i = tid; i < (TT * KK) / 4; i += 192) s4[i] = f4[i];
    }
    for (int i = tid; i < KK * KK; i += 192) strans[i] = trans[i];
    if (tid < 12) sdelta[tid] = (tid == START_ID) ? 0.0f : NEGV;   // t=0 row
    __syncthreads();

    if (tid < 32) {
        const int lane = tid;
        const int ic = lane < KK ? lane : KK - 1;

        float tr[KK];
#pragma unroll
        for (int j = 0; j < KK; j++) tr[j] = strans[ic * KK + j];

        float d[KK];
#pragma unroll
        for (int j = 0; j < KK; j++) d[j] = (j == START_ID) ? 0.0f : NEGV;

        float fbuf[7];
#pragma unroll
        for (int s = 0; s < 7; s++) fbuf[s] = sfeat[(1 + s) * KK + ic];

#define VSTEP(T_, U_)                                                          \
        {                                                                      \
            float f = fbuf[U_];                                                \
            int tn = (T_) + 7; tn = tn > (TT - 1) ? (TT - 1) : tn;             \
            fbuf[U_] = sfeat[tn * KK + ic];                                    \
            float s0 = tr[0] + d[0], s1 = tr[1] + d[1], s2 = tr[2] + d[2];     \
            float s3 = tr[3] + d[3], s4 = tr[4] + d[4], s5 = tr[5] + d[5];     \
            float s6 = tr[6] + d[6], s7 = tr[7] + d[7], s8 = tr[8] + d[8];     \
            float s9 = tr[9] + d[9], s10 = tr[10] + d[10];                     \
            float m01 = fmaxf(s0, s1), m23 = fmaxf(s2, s3);                    \
            float m45 = fmaxf(s4, s5), m67 = fmaxf(s6, s7);                    \
            float m89 = fmaxf(s8, s9);                                         \
            float m = fmaxf(fmaxf(fmaxf(m01, m23), fmaxf(m45, m67)),           \
                            fmaxf(m89, s10));                                  \
            float nd = m + f;                                                  \
            if (lane < KK) sdelta[(T_) * 12 + lane] = nd;  /* off the path */  \
            d[0] = __shfl_sync(0xffffffffu, nd, 0);                            \
            d[1] = __shfl_sync(0xffffffffu, nd, 1);                            \
            d[2] = __shfl_sync(0xffffffffu, nd, 2);                            \
            d[3] = __shfl_sync(0xffffffffu, nd, 3);                            \
            d[4] = __shfl_sync(0xffffffffu, nd, 4);                            \
            d[5] = __shfl_sync(0xffffffffu, nd, 5);                            \
            d[6] = __shfl_sync(0xffffffffu, nd, 6);                            \
            d[7] = __shfl_sync(0xffffffffu, nd, 7);                            \
            d[8] = __shfl_sync(0xffffffffu, nd, 8);                            \
            d[9] = __shfl_sync(0xffffffffu, nd, 9);                            \
            d[10] = __shfl_sync(0xffffffffu, nd, 10);                          \
        }

        int t = 1;
        for (int it = 0; it < 73; ++it) {        // 73 * 7 = 511 steps, t = 1..511
            VSTEP(t, 0); ++t;
            VSTEP(t, 1); ++t;
            VSTEP(t, 2); ++t;
            VSTEP(t, 3); ++t;
            VSTEP(t, 4); ++t;
            VSTEP(t, 5); ++t;
            VSTEP(t, 6); ++t;
        }
#undef VSTEP

        // final score / last tag (all lanes hold identical d[])
        {
            float m01 = fmaxf(d[0], d[1]), m23 = fmaxf(d[2], d[3]);
            float m45 = fmaxf(d[4], d[5]), m67 = fmaxf(d[6], d[7]);
            float m89 = fmaxf(d[8], d[9]);
            float m = fmaxf(fmaxf(fmaxf(m01, m23), fmaxf(m45, m67)),
                            fmaxf(m89, d[10]));
            unsigned msk = 0;
#pragma unroll
            for (int j = 0; j < KK; j++) msk |= (d[j] == m) ? (1u << j) : 0u;
            if (lane == 0) {
                s_score = m;
                s_lasttag = __ffs(msk) - 1;
            }
        }
    }
    __syncthreads();

    // ---- chunked backtrack, psi recomputed from stored deltas ----
    if (tid < 165) {                       // chunks 0..14 x 11 entry tags
        const int c = tid / KK;
        const int e = tid - c * KK;
        const int tb = 32 * c;
        int tag = e;                       // candidate tag at position tb+32
        for (int t = tb + 32; t > tb; --t) {
            tag = psi_step(strans, sdelta, t, tag);
            s_pathseg[c][e][t - 1 - tb] = (unsigned char)tag;
        }
    } else if (tid == 165) {               // chunk 15 from known last tag
        int tag = s_lasttag;
        s_pathseg[15][0][31] = (unsigned char)tag;
        for (int t = TT - 1; t > 480; --t) {
            tag = psi_step(strans, sdelta, t, tag);
            s_pathseg[15][0][t - 1 - 480] = (unsigned char)tag;
        }
    }
    __syncthreads();

    if (tid == 0) {
        s_esel[15] = 0;
        int btag = s_pathseg[15][0][0];    // tag at position 480
        for (int c = 14; c >= 0; --c) {
            s_esel[c] = (unsigned char)btag;
            btag = s_pathseg[c][btag][0];  // tag at position 32c
        }
    }
    __syncthreads();

    if (tid == 0) out[b] = s_score;
    for (int p = tid; p < TT; p += 192) {
        int c = p >> 5;
        out[BB + (size_t)b * TT + p] = (float)s_pathseg[c][s_esel[c]][p & 31];
    }
}

// ---------------------------------------------------------------------------
extern "C" void kernel_launch(void* const* d_in, const int* in_sizes, int n_in,
                              void* d_out, int out_size)
{
    const float* embeds = (const float*)d_in[0];   // [B,T,H]
    const float* W_fc   = (const float*)d_in[1];   // [K,H]
    const float* b_fc   = (const float*)d_in[2];   // [K]
    const float* trans  = (const float*)d_in[3];   // [K,K]
    float* out = (float*)d_out;

    feats_kernel<<<1024, 256>>>(embeds, W_fc, b_fc);
    viterbi_kernel<<<BB, 192>>>(trans, out);
}

// round 7
// speedup vs baseline: 1.9244x; 1.1546x over previous
#include <cuda_runtime.h>
#include <cstdint>

#define BB 64
#define TT 512
#define HH 768
#define KK 11
#define START_ID 9
#define NEGV (-10000.0f)
#define NROWS (BB*TT)            // 32768

__device__ __align__(16) float g_feats[NROWS * KK];

// ---------------------------------------------------------------------------
// Kernel 1: feats[row][k] = dot(A[row,:], W[k,:]) + bias[k]   (at DRAM roofline)
// ---------------------------------------------------------------------------
__global__ __launch_bounds__(256) void feats_kernel(
    const float* __restrict__ A,      // [NROWS, HH]
    const float* __restrict__ W,      // [KK, HH]
    const float* __restrict__ bias)   // [KK]
{
    __shared__ float sWt[HH * KK];    // [h*11 + k], 33792 B

    const int tid = threadIdx.x;
    for (int i = tid; i < HH * KK; i += 256) {
        int k = i / HH, h = i - k * HH;
        sWt[h * KK + k] = W[i];
    }
    __syncthreads();

    const int lane = tid & 31;
    const int warp = tid >> 5;
    const int rowBase = blockIdx.x * 32 + warp * 4;

    float acc[4][KK];
#pragma unroll
    for (int r = 0; r < 4; r++)
#pragma unroll
        for (int k = 0; k < KK; k++) acc[r][k] = 0.0f;

#pragma unroll
    for (int w = 0; w < 6; w++) {
        float a[4][4];
#pragma unroll
        for (int r = 0; r < 4; r++)
#pragma unroll
            for (int s = 0; s < 4; s++)
                a[r][s] = A[(size_t)(rowBase + r) * HH + w * 128 + s * 32 + lane];
#pragma unroll
        for (int s = 0; s < 4; s++) {
            float wr[KK];
            const int hb = (w * 128 + s * 32 + lane) * KK;
#pragma unroll
            for (int k = 0; k < KK; k++) wr[k] = sWt[hb + k];
#pragma unroll
            for (int r = 0; r < 4; r++)
#pragma unroll
                for (int k = 0; k < KK; k++)
                    acc[r][k] = fmaf(a[r][s], wr[k], acc[r][k]);
        }
    }

#pragma unroll
    for (int r = 0; r < 4; r++)
#pragma unroll
        for (int k = 0; k < KK; k++) {
            float v = acc[r][k];
            v += __shfl_xor_sync(0xffffffffu, v, 16);
            v += __shfl_xor_sync(0xffffffffu, v, 8);
            v += __shfl_xor_sync(0xffffffffu, v, 4);
            v += __shfl_xor_sync(0xffffffffu, v, 2);
            v += __shfl_xor_sync(0xffffffffu, v, 1);
            acc[r][k] = v;
        }

    if (lane == 0) {
#pragma unroll
        for (int r = 0; r < 4; r++)
#pragma unroll
            for (int k = 0; k < KK; k++)
                g_feats[(size_t)(rowBase + r) * KK + k] = acc[r][k] + __ldg(&bias[k]);
    }
}

// ---------------------------------------------------------------------------
// psi recompute: argmax_j (trans[tag][j] + delta[t-1][j]), first-max wins.
// Bit-exact vs the scan (same FADDs; max is order-invariant).
// ---------------------------------------------------------------------------
__device__ __forceinline__ int psi_step(const float* __restrict__ strans,
                                        const float* __restrict__ sdelta,
                                        int t, int tag)
{
    const float* tr = strans + tag * KK;
    const float* d = sdelta + (t - 1) * 12;
    float s[KK];
#pragma unroll
    for (int j = 0; j < KK; j++) s[j] = tr[j] + d[j];
    float m = s[0];
#pragma unroll
    for (int j = 1; j < KK; j++) m = fmaxf(m, s[j]);
    unsigned msk = 0;
#pragma unroll
    for (int j = 0; j < KK; j++) msk |= (s[j] == m) ? (1u << j) : 0u;
    return __ffs(msk) - 1;
}

// ---------------------------------------------------------------------------
// Kernel 2: Viterbi. One block per batch.
// Scan: warp 0, fully converged. Per step, lane ic computes new delta for tag
// ic; the history STS into sdelta[t*12+ic] doubles as the broadcast — the warp
// reads the row back with 3x LDS.128 (same-warp LSU wavefronts are ordered, so
// no syncwarp; asm volatile pins compile-time order). Lanes 11..31 duplicate
// lane 10 (same value, same address -> collapsed write), so no branches.
// Then chunked parallel backtrack recomputing psi from the stored deltas.
// ---------------------------------------------------------------------------
__global__ __launch_bounds__(192) void viterbi_kernel(
    const float* __restrict__ trans,   // [KK, KK]
    float* __restrict__ out)           // [BB + BB*TT]
{
    const int b = blockIdx.x;
    const int tid = threadIdx.x;

    __shared__ float sfeat[TT * KK];                  // 22528 B, [t*11+k]
    __shared__ __align__(16) float sdelta[TT * 12];   // 24576 B, [t*12+j]
    __shared__ float strans[KK * KK];                 // 484 B
    __shared__ unsigned char s_pathseg[16][KK][32];   // 5632 B
    __shared__ unsigned char s_esel[16];
    __shared__ int s_lasttag;
    __shared__ float s_score;

    // stage this batch's feats + transitions
    {
        const float4* f4 = reinterpret_cast<const float4*>(g_feats + (size_t)b * TT * KK);
        float4* s4 = reinterpret_cast<float4*>(sfeat);
        for (int i = tid; i < (TT * KK) / 4; i += 192) s4[i] = f4[i];
    }
    for (int i = tid; i < KK * KK; i += 192) strans[i] = trans[i];
    if (tid < 12) sdelta[tid] = (tid == START_ID) ? 0.0f : NEGV;   // t=0 row
    __syncthreads();

    if (tid < 32) {
        const int lane = tid;
        const int ic = lane < KK ? lane : KK - 1;

        float tr[KK];
#pragma unroll
        for (int j = 0; j < KK; j++) tr[j] = strans[ic * KK + j];

        const unsigned sd_base =
            (unsigned)__cvta_generic_to_shared(sdelta);
        const unsigned st_off = sd_base + ic * 4;      // this lane's store slot

        float fbuf[7];
#pragma unroll
        for (int s = 0; s < 7; s++) fbuf[s] = sfeat[(1 + s) * KK + ic];

        // prologue: delta row 0 (after __syncthreads, ordering is safe)
        float d0, d1, d2, d3, d4, d5, d6, d7, d8, d9, d10, dpad;
        asm volatile("ld.shared.v4.f32 {%0,%1,%2,%3}, [%4];"
                     : "=f"(d0), "=f"(d1), "=f"(d2), "=f"(d3) : "r"(sd_base));
        asm volatile("ld.shared.v4.f32 {%0,%1,%2,%3}, [%4];"
                     : "=f"(d4), "=f"(d5), "=f"(d6), "=f"(d7) : "r"(sd_base + 16));
        asm volatile("ld.shared.v4.f32 {%0,%1,%2,%3}, [%4];"
                     : "=f"(d8), "=f"(d9), "=f"(d10), "=f"(dpad) : "r"(sd_base + 32));

#define VSTEP(T_, U_)                                                          \
        {                                                                      \
            float f = fbuf[U_];                                                \
            int tn = (T_) + 7; tn = tn > (TT - 1) ? (TT - 1) : tn;             \
            fbuf[U_] = sfeat[tn * KK + ic];                                    \
            float s0 = tr[0] + d0, s1 = tr[1] + d1, s2 = tr[2] + d2;           \
            float s3 = tr[3] + d3, s4 = tr[4] + d4, s5 = tr[5] + d5;           \
            float s6 = tr[6] + d6, s7 = tr[7] + d7, s8 = tr[8] + d8;           \
            float s9 = tr[9] + d9, s10 = tr[10] + d10;                         \
            float m01 = fmaxf(s0, s1), m23 = fmaxf(s2, s3);                    \
            float m45 = fmaxf(s4, s5), m67 = fmaxf(s6, s7);                    \
            float m89 = fmaxf(s8, s9);                                         \
            float m = fmaxf(fmaxf(fmaxf(m01, m23), fmaxf(m45, m67)),           \
                            fmaxf(m89, s10));                                  \
            float nd = m + f;                                                  \
            asm volatile("st.shared.f32 [%0], %1;"                             \
                         :: "r"(st_off + (T_) * 48), "f"(nd) : "memory");      \
            asm volatile("ld.shared.v4.f32 {%0,%1,%2,%3}, [%4];"               \
                         : "=f"(d0), "=f"(d1), "=f"(d2), "=f"(d3)              \
                         : "r"(sd_base + (T_) * 48) : "memory");               \
            asm volatile("ld.shared.v4.f32 {%0,%1,%2,%3}, [%4];"               \
                         : "=f"(d4), "=f"(d5), "=f"(d6), "=f"(d7)              \
                         : "r"(sd_base + (T_) * 48 + 16) : "memory");          \
            asm volatile("ld.shared.v4.f32 {%0,%1,%2,%3}, [%4];"               \
                         : "=f"(d8), "=f"(d9), "=f"(d10), "=f"(dpad)           \
                         : "r"(sd_base + (T_) * 48 + 32) : "memory");          \
        }

        int t = 1;
        for (int it = 0; it < 73; ++it) {        // 73 * 7 = 511 steps, t = 1..511
            VSTEP(t, 0); ++t;
            VSTEP(t, 1); ++t;
            VSTEP(t, 2); ++t;
            VSTEP(t, 3); ++t;
            VSTEP(t, 4); ++t;
            VSTEP(t, 5); ++t;
            VSTEP(t, 6); ++t;
        }
#undef VSTEP

        // final score / last tag (all lanes hold identical d*)
        {
            float m01 = fmaxf(d0, d1), m23 = fmaxf(d2, d3);
            float m45 = fmaxf(d4, d5), m67 = fmaxf(d6, d7);
            float m89 = fmaxf(d8, d9);
            float m = fmaxf(fmaxf(fmaxf(m01, m23), fmaxf(m45, m67)),
                            fmaxf(m89, d10));
            unsigned msk = (d0 == m ? 1u : 0u) | (d1 == m ? 2u : 0u) |
                           (d2 == m ? 4u : 0u) | (d3 == m ? 8u : 0u) |
                           (d4 == m ? 16u : 0u) | (d5 == m ? 32u : 0u) |
                           (d6 == m ? 64u : 0u) | (d7 == m ? 128u : 0u) |
                           (d8 == m ? 256u : 0u) | (d9 == m ? 512u : 0u) |
                           (d10 == m ? 1024u : 0u);
            if (lane == 0) {
                s_score = m;
                s_lasttag = __ffs(msk) - 1;
            }
        }
    }
    __syncthreads();

    // ---- chunked backtrack, psi recomputed from stored deltas ----
    if (tid < 165) {                       // chunks 0..14 x 11 entry tags
        const int c = tid / KK;
        const int e = tid - c * KK;
        const int tb = 32 * c;
        int tag = e;                       // candidate tag at position tb+32
        for (int t = tb + 32; t > tb; --t) {
            tag = psi_step(strans, sdelta, t, tag);
            s_pathseg[c][e][t - 1 - tb] = (unsigned char)tag;
        }
    } else if (tid == 165) {               // chunk 15 from known last tag
        int tag = s_lasttag;
        s_pathseg[15][0][31] = (unsigned char)tag;
        for (int t = TT - 1; t > 480; --t) {
            tag = psi_step(strans, sdelta, t, tag);
            s_pathseg[15][0][t - 1 - 480] = (unsigned char)tag;
        }
    }
    __syncthreads();

    if (tid == 0) {
        s_esel[15] = 0;
        int btag = s_pathseg[15][0][0];    // tag at position 480
        for (int c = 14; c >= 0; --c) {
            s_esel[c] = (unsigned char)btag;
            btag = s_pathseg[c][btag][0];  // tag at position 32c
        }
    }
    __syncthreads();

    if (tid == 0) out[b] = s_score;
    for (int p = tid; p < TT; p += 192) {
        int c = p >> 5;
        out[BB + (size_t)b * TT + p] = (float)s_pathseg[c][s_esel[c]][p & 31];
    }
}

// ---------------------------------------------------------------------------
extern "C" void kernel_launch(void* const* d_in, const int* in_sizes, int n_in,
                              void* d_out, int out_size)
{
    const float* embeds = (const float*)d_in[0];   // [B,T,H]
    const float* W_fc   = (const float*)d_in[1];   // [K,H]
    const float* b_fc   = (const float*)d_in[2];   // [K]
    const float* trans  = (const float*)d_in[3];   // [K,K]
    float* out = (float*)d_out;

    feats_kernel<<<1024, 256>>>(embeds, W_fc, b_fc);
    viterbi_kernel<<<BB, 192>>>(trans, out);
}

// round 8
// speedup vs baseline: 1.9385x; 1.0073x over previous
#include <cuda_runtime.h>
#include <cstdint>

#define BB 64
#define TT 512
#define HH 768
#define KK 11
#define START_ID 9
#define END_ID 10
#define NEGV (-10000.0f)
#define NROWS (BB*TT)            // 32768

__device__ __align__(16) float g_feats[NROWS * KK];

// ---------------------------------------------------------------------------
// Kernel 1: feats[row][k] = dot(A[row,:], W[k,:]) + bias[k]   (L2/DRAM bound)
// ---------------------------------------------------------------------------
__global__ __launch_bounds__(256) void feats_kernel(
    const float* __restrict__ A,      // [NROWS, HH]
    const float* __restrict__ W,      // [KK, HH]
    const float* __restrict__ bias)   // [KK]
{
    __shared__ float sWt[HH * KK];    // [h*11 + k], 33792 B

    const int tid = threadIdx.x;
    for (int i = tid; i < HH * KK; i += 256) {
        int k = i / HH, h = i - k * HH;
        sWt[h * KK + k] = W[i];
    }
    __syncthreads();

    const int lane = tid & 31;
    const int warp = tid >> 5;
    const int rowBase = blockIdx.x * 32 + warp * 4;

    float acc[4][KK];
#pragma unroll
    for (int r = 0; r < 4; r++)
#pragma unroll
        for (int k = 0; k < KK; k++) acc[r][k] = 0.0f;

#pragma unroll
    for (int w = 0; w < 6; w++) {
        float a[4][4];
#pragma unroll
        for (int r = 0; r < 4; r++)
#pragma unroll
            for (int s = 0; s < 4; s++)
                a[r][s] = A[(size_t)(rowBase + r) * HH + w * 128 + s * 32 + lane];
#pragma unroll
        for (int s = 0; s < 4; s++) {
            float wr[KK];
            const int hb = (w * 128 + s * 32 + lane) * KK;
#pragma unroll
            for (int k = 0; k < KK; k++) wr[k] = sWt[hb + k];
#pragma unroll
            for (int r = 0; r < 4; r++)
#pragma unroll
                for (int k = 0; k < KK; k++)
                    acc[r][k] = fmaf(a[r][s], wr[k], acc[r][k]);
        }
    }

#pragma unroll
    for (int r = 0; r < 4; r++)
#pragma unroll
        for (int k = 0; k < KK; k++) {
            float v = acc[r][k];
            v += __shfl_xor_sync(0xffffffffu, v, 16);
            v += __shfl_xor_sync(0xffffffffu, v, 8);
            v += __shfl_xor_sync(0xffffffffu, v, 4);
            v += __shfl_xor_sync(0xffffffffu, v, 2);
            v += __shfl_xor_sync(0xffffffffu, v, 1);
            acc[r][k] = v;
        }

    if (lane == 0) {
#pragma unroll
        for (int r = 0; r < 4; r++)
#pragma unroll
            for (int k = 0; k < KK; k++)
                g_feats[(size_t)(rowBase + r) * KK + k] = acc[r][k] + __ldg(&bias[k]);
    }
}

// ---------------------------------------------------------------------------
// psi recompute: argmax_j (trans[tag][j] + delta[t-1][j]), first-max wins.
// Only j=0..8 can win for t>=2 (START/END predecessors masked to -1e4 and
// certainly lose); at t=1 the winner is START for every target (d0[START]=0,
// all others -1e4). Bit-exact vs reference argmax.
// ---------------------------------------------------------------------------
__device__ __forceinline__ int psi_step(const float* __restrict__ strans,
                                        const float* __restrict__ sdelta,
                                        int t, int tag)
{
    if (t == 1) return START_ID;
    const float* tr = strans + tag * KK;
    const float* d = sdelta + (t - 1) * 12;
    float s[9];
#pragma unroll
    for (int j = 0; j < 9; j++) s[j] = tr[j] + d[j];
    float m = s[0];
#pragma unroll
    for (int j = 1; j < 9; j++) m = fmaxf(m, s[j]);
    unsigned msk = 0;
#pragma unroll
    for (int j = 0; j < 9; j++) msk |= (s[j] == m) ? (1u << j) : 0u;
    return __ffs(msk) - 1;
}

// ---------------------------------------------------------------------------
// Kernel 2: Viterbi. One block per batch.
// Warp 0 scan, dead tags eliminated: 9 live predecessors (j=0..8), 10 targets
// (0..8 + END in slot 9). Row exchange = STS + 2xLDS.128 + LDS.32, with the
// late LDS.32 (s8) merged at tree depth 1. t=1 is a closed-form special step.
// Backtrack recomputes psi from the stored delta rows (chunked, parallel).
// ---------------------------------------------------------------------------
__global__ __launch_bounds__(192) void viterbi_kernel(
    const float* __restrict__ trans,   // [KK, KK]
    float* __restrict__ out)           // [BB + BB*TT]
{
    const int b = blockIdx.x;
    const int tid = threadIdx.x;

    __shared__ float sfeat[(TT + 8) * KK];            // 22880 B (8 pad rows)
    __shared__ __align__(16) float sdelta[TT * 12];   // 24576 B, [t*12 + slot]
    __shared__ float strans[KK * KK];                 // 484 B
    __shared__ unsigned char s_pathseg[16][KK][32];   // 5632 B
    __shared__ unsigned char s_esel[16];
    __shared__ int s_lasttag;
    __shared__ float s_score;

    // stage this batch's feats + transitions
    {
        const float4* f4 = reinterpret_cast<const float4*>(g_feats + (size_t)b * TT * KK);
        float4* s4 = reinterpret_cast<float4*>(sfeat);
        for (int i = tid; i < (TT * KK) / 4; i += 192) s4[i] = f4[i];
    }
    for (int i = tid; i < KK * KK; i += 192) strans[i] = trans[i];
    __syncthreads();

    if (tid < 32) {
        const int lane = tid;
        const int target = (lane <= 8) ? lane : END_ID;       // lanes 9..31 -> END
        const int slot4 = ((lane <= 8) ? lane : 9) * 4;       // END stored in slot 9

        float tr0 = strans[target * KK + 0], tr1 = strans[target * KK + 1];
        float tr2 = strans[target * KK + 2], tr3 = strans[target * KK + 3];
        float tr4 = strans[target * KK + 4], tr5 = strans[target * KK + 5];
        float tr6 = strans[target * KK + 6], tr7 = strans[target * KK + 7];
        float tr8 = strans[target * KK + 8], tr9 = strans[target * KK + 9];

        unsigned sd_base = (unsigned)__cvta_generic_to_shared(sdelta);
        unsigned addr = sd_base + 48;                          // row 1

        // ---- t = 1 special step: winner predecessor is START (certain) ----
        float nd1 = (tr9 + 0.0f) + sfeat[KK + target];
        asm volatile("st.shared.f32 [%0], %1;" :: "r"(addr + slot4), "f"(nd1) : "memory");
        float d0, d1, d2, d3, d4, d5, d6, d7, d8;
        asm volatile("ld.shared.v4.f32 {%0,%1,%2,%3}, [%4];"
                     : "=f"(d0), "=f"(d1), "=f"(d2), "=f"(d3) : "r"(addr) : "memory");
        asm volatile("ld.shared.v4.f32 {%0,%1,%2,%3}, [%4];"
                     : "=f"(d4), "=f"(d5), "=f"(d6), "=f"(d7) : "r"(addr + 16) : "memory");
        asm volatile("ld.shared.f32 %0, [%1];"
                     : "=f"(d8) : "r"(addr + 32) : "memory");

        float fbuf[6];
#pragma unroll
        for (int s = 0; s < 6; s++) fbuf[s] = sfeat[(2 + s) * KK + target];
        const float* fpre = sfeat + 8 * KK + target;

#define VSTEP(U_)                                                              \
        {                                                                      \
            float f = fbuf[U_];                                                \
            fbuf[U_] = *fpre; fpre += KK;                                      \
            float s0 = tr0 + d0, s1 = tr1 + d1, s2 = tr2 + d2, s3 = tr3 + d3;  \
            float s4 = tr4 + d4, s5 = tr5 + d5, s6 = tr6 + d6, s7 = tr7 + d7;  \
            float s8v = tr8 + d8;                                              \
            float a2 = fmaxf(s0, s1), b2 = fmaxf(s2, s3);                      \
            float c2 = fmaxf(s4, s5), e2 = fmaxf(s6, s7);                      \
            float ab = fmaxf(a2, b2), ce = fmaxf(c2, e2);                      \
            float m = fmaxf(fmaxf(ab, ce), s8v);                               \
            float nd = m + f;                                                  \
            asm volatile("st.shared.f32 [%0], %1;"                             \
                         :: "r"(addr + 48 + slot4), "f"(nd) : "memory");       \
            asm volatile("ld.shared.v4.f32 {%0,%1,%2,%3}, [%4];"               \
                         : "=f"(d0), "=f"(d1), "=f"(d2), "=f"(d3)              \
                         : "r"(addr + 48) : "memory");                         \
            asm volatile("ld.shared.v4.f32 {%0,%1,%2,%3}, [%4];"               \
                         : "=f"(d4), "=f"(d5), "=f"(d6), "=f"(d7)              \
                         : "r"(addr + 64) : "memory");                         \
            asm volatile("ld.shared.f32 %0, [%1];"                             \
                         : "=f"(d8) : "r"(addr + 80) : "memory");              \
            addr += 48;                                                        \
        }

        for (int it = 0; it < 85; ++it) {       // 85 * 6 = 510 steps, t = 2..511
            VSTEP(0) VSTEP(1) VSTEP(2) VSTEP(3) VSTEP(4) VSTEP(5)
        }
#undef VSTEP

        // d0..d8 = live deltas at t=511; END delta sits in slot 9 of row 511
        float dEND;
        asm volatile("ld.shared.f32 %0, [%1];" : "=f"(dEND) : "r"(addr + 36) : "memory");

        {
            float m01 = fmaxf(d0, d1), m23 = fmaxf(d2, d3);
            float m45 = fmaxf(d4, d5), m67 = fmaxf(d6, d7);
            float m = fmaxf(fmaxf(fmaxf(m01, m23), fmaxf(m45, m67)),
                            fmaxf(d8, dEND));
            unsigned msk = (d0 == m ? 1u : 0u) | (d1 == m ? 2u : 0u) |
                           (d2 == m ? 4u : 0u) | (d3 == m ? 8u : 0u) |
                           (d4 == m ? 16u : 0u) | (d5 == m ? 32u : 0u) |
                           (d6 == m ? 64u : 0u) | (d7 == m ? 128u : 0u) |
                           (d8 == m ? 256u : 0u) |
                           (dEND == m ? (1u << END_ID) : 0u);
            if (lane == 0) {
                s_score = m;
                s_lasttag = __ffs(msk) - 1;
            }
        }
    }
    __syncthreads();

    // ---- chunked backtrack, psi recomputed from stored deltas ----
    if (tid < 165) {                       // chunks 0..14 x 11 entry tags
        const int c = tid / KK;
        const int e = tid - c * KK;
        const int tb = 32 * c;
        int tag = e;                       // candidate tag at position tb+32
        for (int t = tb + 32; t > tb; --t) {
            tag = psi_step(strans, sdelta, t, tag);
            s_pathseg[c][e][t - 1 - tb] = (unsigned char)tag;
        }
    } else if (tid == 165) {               // chunk 15 from known last tag
        int tag = s_lasttag;
        s_pathseg[15][0][31] = (unsigned char)tag;
        for (int t = TT - 1; t > 480; --t) {
            tag = psi_step(strans, sdelta, t, tag);
            s_pathseg[15][0][t - 1 - 480] = (unsigned char)tag;
        }
    }
    __syncthreads();

    if (tid == 0) {
        s_esel[15] = 0;
        int btag = s_pathseg[15][0][0];    // tag at position 480
        for (int c = 14; c >= 0; --c) {
            s_esel[c] = (unsigned char)btag;
            btag = s_pathseg[c][btag][0];  // tag at position 32c
        }
    }
    __syncthreads();

    if (tid == 0) out[b] = s_score;
    for (int p = tid; p < TT; p += 192) {
        int c = p >> 5;
        out[BB + (size_t)b * TT + p] = (float)s_pathseg[c][s_esel[c]][p & 31];
    }
}

// ---------------------------------------------------------------------------
extern "C" void kernel_launch(void* const* d_in, const int* in_sizes, int n_in,
                              void* d_out, int out_size)
{
    const float* embeds = (const float*)d_in[0];   // [B,T,H]
    const float* W_fc   = (const float*)d_in[1];   // [K,H]
    const float* b_fc   = (const float*)d_in[2];   // [K]
    const float* trans  = (const float*)d_in[3];   // [K,K]
    float* out = (float*)d_out;

    feats_kernel<<<1024, 256>>>(embeds, W_fc, b_fc);
    viterbi_kernel<<<BB, 192>>>(trans, out);
}